// round 3
// baseline (speedup 1.0000x reference)
#include <cuda_runtime.h>
#include <limits.h>

#define W_IMG 1024
#define H_IMG 1024
#define C_IMG 3
#define PLANE (H_IMG * W_IMG)

#define TW 32
#define TH 16
#define BLOCK (TW * TH)      // 512 threads
#define CAP 8192             // smem floats (32 KB) for the staged footprint

__global__ __launch_bounds__(BLOCK) void homography_warp_kernel(
    const float* __restrict__ img,    // [N, C, H, W]
    const float* __restrict__ homo,   // [N, 3, 3]
    float* __restrict__ out)          // [N, C, H, W]
{
    const int n   = blockIdx.z;
    const int tid = threadIdx.x;
    const int w   = blockIdx.x * TW + (tid & (TW - 1));
    const int h   = blockIdx.y * TH + (tid >> 5);

    __shared__ float Hs[9];
    __shared__ int s_xmn, s_xmx, s_ymn, s_ymx;
    __shared__ float buf[CAP];

    if (tid < 9) Hs[tid] = homo[n * 9 + tid];
    if (tid == 0) {
        s_xmn = INT_MAX; s_xmx = INT_MIN;
        s_ymn = INT_MAX; s_ymx = INT_MIN;
    }
    __syncthreads();

    // Normalized grid coords in [-1, 1] (align_corners=True).
    const float gx = (float)w * (2.0f / 1023.0f) - 1.0f;
    const float gy = (float)h * (2.0f / 1023.0f) - 1.0f;

    const float X = Hs[0] * gx + Hs[1] * gy + Hs[2];
    const float Y = Hs[3] * gx + Hs[4] * gy + Hs[5];
    const float Z = Hs[6] * gx + Hs[7] * gy + Hs[8];
    const float inv = 1.0f / Z;

    const float x = (X * inv + 1.0f) * (0.5f * (float)(W_IMG - 1));
    const float y = (Y * inv + 1.0f) * (0.5f * (float)(H_IMG - 1));

    const float x0f = floorf(x);
    const float y0f = floorf(y);
    const int x0 = (int)x0f;
    const int y0 = (int)y0f;

    const float wx1 = x - x0f;
    const float wx0 = 1.0f - wx1;
    const float wy1 = y - y0f;
    const float wy0 = 1.0f - wy1;

    // Block-wide footprint bounds.
    {
        const int rxmn = __reduce_min_sync(0xFFFFFFFFu, x0);
        const int rxmx = __reduce_max_sync(0xFFFFFFFFu, x0);
        const int rymn = __reduce_min_sync(0xFFFFFFFFu, y0);
        const int rymx = __reduce_max_sync(0xFFFFFFFFu, y0);
        if ((tid & 31) == 0) {
            atomicMin(&s_xmn, rxmn); atomicMax(&s_xmx, rxmx);
            atomicMin(&s_ymn, rymn); atomicMax(&s_ymx, rymx);
        }
    }
    __syncthreads();

    const int xmn = s_xmn, xmx = s_xmx, ymn = s_ymn, ymx = s_ymx;

    bool ok = (xmn >= 0) & (xmx <= W_IMG - 2) & (ymn >= 0) & (ymx <= H_IMG - 2);
    int FW = 0, FH = 0, total = 0;
    if (ok) {
        FW = xmx - xmn + 2;       // corners span xmn .. xmx+1
        FH = ymx - ymn + 2;
        total = FH * FW;
        ok = (total <= CAP);
    }

    const float* base = img + n * (C_IMG * PLANE);
    float* ob = out + n * (C_IMG * PLANE) + h * W_IMG + w;

    if (ok) {
        // ---- smem tile path (whole block, uniform branch) ----
        const float w00 = wx0 * wy0;
        const float w01 = wx1 * wy0;
        const float w10 = wx0 * wy1;
        const float w11 = wx1 * wy1;

        const int a = (y0 - ymn) * FW + (x0 - xmn);
        const unsigned magic = 0xFFFFFFFFu / (unsigned)FW + 1;  // exact div for i < 2^16
        const float* src0 = base + ymn * W_IMG + xmn;

#pragma unroll 1
        for (int c = 0; c < C_IMG; ++c) {
            const float* sc = src0 + c * PLANE;
            __syncthreads();                       // buf free from previous channel
            for (int i = tid; i < total; i += BLOCK) {
                const int r   = (int)__umulhi((unsigned)i, magic);
                const int col = i - r * FW;
                buf[i] = __ldg(sc + r * W_IMG + col);
            }
            __syncthreads();                       // buf filled
            const float v = buf[a]          * w00
                          + buf[a + 1]      * w01
                          + buf[a + FW]     * w10
                          + buf[a + FW + 1] * w11;
            ob[c * PLANE] = v;
        }
    } else {
        // ---- fallback: fully masked/clamped zeros-padding path ----
        const int x1 = x0 + 1;
        const int y1 = y0 + 1;

        const bool vx0 = (x0 >= 0) & (x0 < W_IMG);
        const bool vx1 = (x1 >= 0) & (x1 < W_IMG);
        const bool vy0 = (y0 >= 0) & (y0 < H_IMG);
        const bool vy1 = (y1 >= 0) & (y1 < H_IMG);

        const int x0c = min(max(x0, 0), W_IMG - 1);
        const int x1c = min(max(x1, 0), W_IMG - 1);
        const int y0c = min(max(y0, 0), H_IMG - 1);
        const int y1c = min(max(y1, 0), H_IMG - 1);

        const float w00 = (vx0 && vy0) ? (wx0 * wy0) : 0.0f;
        const float w01 = (vx1 && vy0) ? (wx1 * wy0) : 0.0f;
        const float w10 = (vx0 && vy1) ? (wx0 * wy1) : 0.0f;
        const float w11 = (vx1 && vy1) ? (wx1 * wy1) : 0.0f;

        const int r0 = y0c * W_IMG;
        const int r1 = y1c * W_IMG;

#pragma unroll
        for (int c = 0; c < C_IMG; ++c) {
            const float* p = base + c * PLANE;
            const float v = __ldg(p + r0 + x0c) * w00
                          + __ldg(p + r0 + x1c) * w01
                          + __ldg(p + r1 + x0c) * w10
                          + __ldg(p + r1 + x1c) * w11;
            ob[c * PLANE] = v;
        }
    }
}

extern "C" void kernel_launch(void* const* d_in, const int* in_sizes, int n_in,
                              void* d_out, int out_size) {
    const float* patch_src    = (const float*)d_in[0];  // [16,3,1024,1024]
    const float* dst_homo_src = (const float*)d_in[1];  // [16,3,3]
    float* out = (float*)d_out;

    dim3 grid(W_IMG / TW, H_IMG / TH, 16);
    homography_warp_kernel<<<grid, BLOCK>>>(patch_src, dst_homo_src, out);
}

// round 4
// speedup vs baseline: 2.3730x; 2.3730x over previous
#include <cuda_runtime.h>

#define W_IMG 1024
#define H_IMG 1024
#define C_IMG 3
#define PLANE (H_IMG * W_IMG)

#define RPT 4                 // rows per thread
#define WARPS 8               // 256 threads -> tile 32 wide x 32 tall
#define BLOCK (32 * WARPS)

__global__ __launch_bounds__(BLOCK) void homography_warp_kernel(
    const float* __restrict__ img,    // [N, C, H, W]
    const float* __restrict__ homo,   // [N, 3, 3]
    float* __restrict__ out)          // [N, C, H, W]
{
    const int n    = blockIdx.z;
    const int lane = threadIdx.x & 31;
    const int wrp  = threadIdx.x >> 5;
    const int w    = blockIdx.x * 32 + lane;
    const int h0   = (blockIdx.y * WARPS + wrp) * RPT;

    __shared__ float Hs[9];
    if (threadIdx.x < 9) Hs[threadIdx.x] = homo[n * 9 + threadIdx.x];
    __syncthreads();

    const float gx  = (float)w  * (2.0f / 1023.0f) - 1.0f;
    const float gy0 = (float)h0 * (2.0f / 1023.0f) - 1.0f;
    const float dg  = 2.0f / 1023.0f;

    // Base transform at row h0, then increment by column of H per row.
    float Xr = Hs[0] * gx + Hs[1] * gy0 + Hs[2];
    float Yr = Hs[3] * gx + Hs[4] * gy0 + Hs[5];
    float Zr = Hs[6] * gx + Hs[7] * gy0 + Hs[8];
    const float dX = Hs[1] * dg;
    const float dY = Hs[4] * dg;
    const float dZ = Hs[7] * dg;

    int   x0[RPT], y0[RPT];
    float wx0[RPT], wx1[RPT], wy0[RPT], wy1[RPT];
    bool  inter = true;

#pragma unroll
    for (int i = 0; i < RPT; i++) {
        const float inv = __fdividef(1.0f, Zr);
        const float x = (Xr * inv + 1.0f) * (0.5f * (float)(W_IMG - 1));
        const float y = (Yr * inv + 1.0f) * (0.5f * (float)(H_IMG - 1));
        const float x0f = floorf(x);
        const float y0f = floorf(y);
        x0[i] = (int)x0f;
        y0[i] = (int)y0f;
        wx1[i] = x - x0f;  wx0[i] = 1.0f - wx1[i];
        wy1[i] = y - y0f;  wy0[i] = 1.0f - wy1[i];
        inter &= (x0[i] >= 0) & (x0[i] <= W_IMG - 2) & (y0[i] >= 0) & (y0[i] <= H_IMG - 2);
        Xr += dX; Yr += dY; Zr += dZ;
    }

    // Channel-1-anchored bases: channel offsets are +-PLANE (4MB), in LDG imm range.
    const float* pc1 = img + n * (C_IMG * PLANE) + PLANE;
    float*       oc1 = out + n * (C_IMG * PLANE) + PLANE + h0 * W_IMG + w;

    if (__all_sync(0xFFFFFFFFu, inter)) {
        // ---- fast path: per-pixel gather bases; vertical tap-pair reuse ----
        const float* q[RPT];
#pragma unroll
        for (int i = 0; i < RPT; i++)
            q[i] = pc1 + (y0[i] * W_IMG + x0[i]);

        bool share[RPT];
        share[0] = false;
#pragma unroll
        for (int i = 1; i < RPT; i++)
            share[i] = (y0[i] == y0[i - 1] + 1) & (x0[i] == x0[i - 1]);

#pragma unroll
        for (int c = -1; c <= 1; c++) {
            const int co = c * PLANE;
            float t0 = 0.0f, t1 = 0.0f;
#pragma unroll
            for (int i = 0; i < RPT; i++) {
                if (i == 0 || !share[i]) {      // predicated reload when chain breaks
                    t0 = q[i][co];
                    t1 = q[i][co + 1];
                }
                const float b0 = q[i][co + W_IMG];
                const float b1 = q[i][co + W_IMG + 1];
                const float vt = t0 * wx0[i] + t1 * wx1[i];
                const float vb = b0 * wx0[i] + b1 * wx1[i];
                oc1[co + i * W_IMG] = vt * wy0[i] + vb * wy1[i];
                t0 = b0; t1 = b1;               // candidate reuse for next row
            }
        }
    } else {
        // ---- slow path: fully masked/clamped zeros-padding semantics ----
#pragma unroll
        for (int i = 0; i < RPT; i++) {
            const int xa = x0[i], ya = y0[i];
            const int xb = xa + 1, yb = ya + 1;

            const bool vx0 = (xa >= 0) & (xa < W_IMG);
            const bool vx1 = (xb >= 0) & (xb < W_IMG);
            const bool vy0 = (ya >= 0) & (ya < H_IMG);
            const bool vy1 = (yb >= 0) & (yb < H_IMG);

            const int x0c = min(max(xa, 0), W_IMG - 1);
            const int x1c = min(max(xb, 0), W_IMG - 1);
            const int y0c = min(max(ya, 0), H_IMG - 1);
            const int y1c = min(max(yb, 0), H_IMG - 1);

            const float w00 = (vx0 && vy0) ? (wx0[i] * wy0[i]) : 0.0f;
            const float w01 = (vx1 && vy0) ? (wx1[i] * wy0[i]) : 0.0f;
            const float w10 = (vx0 && vy1) ? (wx0[i] * wy1[i]) : 0.0f;
            const float w11 = (vx1 && vy1) ? (wx1[i] * wy1[i]) : 0.0f;

            const int r0 = y0c * W_IMG;
            const int r1 = y1c * W_IMG;

#pragma unroll
            for (int c = -1; c <= 1; c++) {
                const int co = c * PLANE;
                const float v = pc1[co + r0 + x0c] * w00
                              + pc1[co + r0 + x1c] * w01
                              + pc1[co + r1 + x0c] * w10
                              + pc1[co + r1 + x1c] * w11;
                oc1[co + i * W_IMG] = v;
            }
        }
    }
}

extern "C" void kernel_launch(void* const* d_in, const int* in_sizes, int n_in,
                              void* d_out, int out_size) {
    const float* patch_src    = (const float*)d_in[0];  // [16,3,1024,1024]
    const float* dst_homo_src = (const float*)d_in[1];  // [16,3,3]
    float* out = (float*)d_out;

    dim3 grid(W_IMG / 32, H_IMG / (WARPS * RPT), 16);
    homography_warp_kernel<<<grid, BLOCK>>>(patch_src, dst_homo_src, out);
}

// round 5
// speedup vs baseline: 2.7237x; 1.1478x over previous
#include <cuda_runtime.h>

#define W_IMG 1024
#define H_IMG 1024
#define C_IMG 3
#define PLANE (H_IMG * W_IMG)

#define RPT 4                 // rows per thread
#define WARPS 8               // 256 threads -> tile 32 wide x 32 tall
#define BLOCK (32 * WARPS)

__global__ __launch_bounds__(BLOCK, 8) void homography_warp_kernel(
    const float* __restrict__ img,    // [N, C, H, W]
    const float* __restrict__ homo,   // [N, 3, 3]
    float* __restrict__ out)          // [N, C, H, W]
{
    const int n    = blockIdx.z;
    const int lane = threadIdx.x & 31;
    const int wrp  = threadIdx.x >> 5;
    const int w    = blockIdx.x * 32 + lane;
    const int h0   = (blockIdx.y * WARPS + wrp) * RPT;

    __shared__ float Hs[9];
    if (threadIdx.x < 9) Hs[threadIdx.x] = homo[n * 9 + threadIdx.x];
    __syncthreads();

    const float gx  = (float)w  * (2.0f / 1023.0f) - 1.0f;
    const float gy0 = (float)h0 * (2.0f / 1023.0f) - 1.0f;
    const float dg  = 2.0f / 1023.0f;

    // Transform at row h0; per-row increment = second column of H * dg.
    float Xr = Hs[0] * gx + Hs[1] * gy0 + Hs[2];
    float Yr = Hs[3] * gx + Hs[4] * gy0 + Hs[5];
    float Zr = Hs[6] * gx + Hs[7] * gy0 + Hs[8];
    const float dX = Hs[1] * dg;
    const float dY = Hs[4] * dg;
    const float dZ = Hs[7] * dg;

    int   off[RPT];            // y0*1024 + x0 (packed)
    float fx[RPT], fy[RPT];    // fractional weights (wx1, wy1)
    bool  inter = true;

    {
        float Xi = Xr, Yi = Yr, Zi = Zr;
#pragma unroll
        for (int i = 0; i < RPT; i++) {
            const float inv = __fdividef(1.0f, Zi);
            const float x = (Xi * inv + 1.0f) * (0.5f * (float)(W_IMG - 1));
            const float y = (Yi * inv + 1.0f) * (0.5f * (float)(H_IMG - 1));
            const float x0f = floorf(x);
            const float y0f = floorf(y);
            const int x0 = (int)x0f;
            const int y0 = (int)y0f;
            fx[i] = x - x0f;
            fy[i] = y - y0f;
            off[i] = y0 * W_IMG + x0;
            inter &= (x0 >= 0) & (x0 <= W_IMG - 2) & (y0 >= 0) & (y0 <= H_IMG - 2);
            Xi += dX; Yi += dY; Zi += dZ;
        }
    }

    // Channel-1-anchored bases: channel offsets +-PLANE (4MB) fit LDG/STG immediates.
    const float* pc1 = img + n * (C_IMG * PLANE) + PLANE;
    float*       oc1 = out + n * (C_IMG * PLANE) + PLANE + h0 * W_IMG + w;

    if (__all_sync(0xFFFFFFFFu, inter)) {
        // ---- fast path: vertical tap-pair reuse, lerp blending ----
        bool share[RPT];
        share[0] = false;
#pragma unroll
        for (int i = 1; i < RPT; i++)
            share[i] = (off[i] == off[i - 1] + W_IMG);

#pragma unroll
        for (int c = -1; c <= 1; c++) {
            const int co = c * PLANE;
            float t0 = 0.0f, t1 = 0.0f;
#pragma unroll
            for (int i = 0; i < RPT; i++) {
                const float* p = pc1 + off[i] + co;
                if (i == 0 || !share[i]) {        // predicated reload when chain breaks
                    t0 = p[0];
                    t1 = p[1];
                }
                const float b0 = p[W_IMG];
                const float b1 = p[W_IMG + 1];
                const float vt = fmaf(fx[i], t1 - t0, t0);
                const float vb = fmaf(fx[i], b1 - b0, b0);
                oc1[co + i * W_IMG] = fmaf(fy[i], vb - vt, vt);
                t0 = b0; t1 = b1;                 // candidate reuse for next row
            }
        }
    } else {
        // ---- slow path (rare boundary warps): recompute; full zeros-padding ----
#pragma unroll 1
        for (int i = 0; i < RPT; i++) {
            const float inv = __fdividef(1.0f, Zr);
            const float x = (Xr * inv + 1.0f) * (0.5f * (float)(W_IMG - 1));
            const float y = (Yr * inv + 1.0f) * (0.5f * (float)(H_IMG - 1));
            Xr += dX; Yr += dY; Zr += dZ;

            const float x0f = floorf(x);
            const float y0f = floorf(y);
            const int xa = (int)x0f, ya = (int)y0f;
            const int xb = xa + 1,   yb = ya + 1;

            const float wx1 = x - x0f, wx0 = 1.0f - wx1;
            const float wy1 = y - y0f, wy0 = 1.0f - wy1;

            const bool vx0 = (xa >= 0) & (xa < W_IMG);
            const bool vx1 = (xb >= 0) & (xb < W_IMG);
            const bool vy0 = (ya >= 0) & (ya < H_IMG);
            const bool vy1 = (yb >= 0) & (yb < H_IMG);

            const int x0c = min(max(xa, 0), W_IMG - 1);
            const int x1c = min(max(xb, 0), W_IMG - 1);
            const int y0c = min(max(ya, 0), H_IMG - 1);
            const int y1c = min(max(yb, 0), H_IMG - 1);

            const float w00 = (vx0 && vy0) ? (wx0 * wy0) : 0.0f;
            const float w01 = (vx1 && vy0) ? (wx1 * wy0) : 0.0f;
            const float w10 = (vx0 && vy1) ? (wx0 * wy1) : 0.0f;
            const float w11 = (vx1 && vy1) ? (wx1 * wy1) : 0.0f;

            const int r0 = y0c * W_IMG;
            const int r1 = y1c * W_IMG;

#pragma unroll
            for (int c = -1; c <= 1; c++) {
                const int co = c * PLANE;
                const float v = pc1[co + r0 + x0c] * w00
                              + pc1[co + r0 + x1c] * w01
                              + pc1[co + r1 + x0c] * w10
                              + pc1[co + r1 + x1c] * w11;
                oc1[co + i * W_IMG] = v;
            }
        }
    }
}

extern "C" void kernel_launch(void* const* d_in, const int* in_sizes, int n_in,
                              void* d_out, int out_size) {
    const float* patch_src    = (const float*)d_in[0];  // [16,3,1024,1024]
    const float* dst_homo_src = (const float*)d_in[1];  // [16,3,3]
    float* out = (float*)d_out;

    dim3 grid(W_IMG / 32, H_IMG / (WARPS * RPT), 16);
    homography_warp_kernel<<<grid, BLOCK>>>(patch_src, dst_homo_src, out);
}